// round 1
// baseline (speedup 1.0000x reference)
#include <cuda_runtime.h>
#include <cstdint>
#include <cstddef>

#define B_ 4
#define V_ 64
#define E_ 1024
#define L_ 1024
#define D_ 256
#define BE_ (B_*E_)
#define SLOTS 16
#define MAXE 32

// ---------------- device scratch (no allocations allowed) ----------------
__device__ float g_M[D_*D_];        // M = Wq^T Wk
__device__ float g_u[D_];           // u = Wq^T bk
__device__ float g_t[D_];           // t = Wk^T bq
__device__ float g_c;               // bq . bk
__device__ int   g_ndeg[V_];        // unique-neighbor count per src
__device__ int   g_ecnt[V_];        // raw edge count per src
__device__ int   g_ndst[V_*SLOTS];  // unique dst per (src, slot)
__device__ int   g_vedge[V_*MAXE];  // raw edge ids per src
__device__ int   g_eslot[E_];       // edge -> slot within its src
__device__ float g_adjw[B_*V_*SLOTS]; // summed edge weight per (b, src, slot)

__device__ __forceinline__ float2 u64_to_f2(unsigned long long a) {
    float2 r;
    asm("mov.b64 {%0, %1}, %2;" : "=f"(r.x), "=f"(r.y) : "l"(a));
    return r;
}

// ---------------- K0: M, u, t, c ----------------
__global__ void k0_prep(const float* __restrict__ Wq, const float* __restrict__ bq,
                        const float* __restrict__ Wk, const float* __restrict__ bk) {
    __shared__ float swk[D_];
    const int j = blockIdx.x, d = threadIdx.x;
    swk[d] = Wk[d*D_ + j];          // Wk[k=d][j]
    __syncthreads();
    float acc = 0.f;
#pragma unroll 8
    for (int k = 0; k < D_; ++k) acc += Wq[k*D_ + d] * swk[k];
    g_M[d*D_ + j] = acc;
    if (d == 0) {
        float s = 0.f;
        for (int k = 0; k < D_; ++k) s += bq[k] * swk[k];
        g_t[j] = s;
    }
    if (j == 0) {
        float s = 0.f;
        for (int k = 0; k < D_; ++k) s += Wq[k*D_ + d] * bk[k];
        g_u[d] = s;
    }
    if (j == 0 && d == 0) {
        float s = 0.f;
        for (int k = 0; k < D_; ++k) s += bq[k] * bk[k];
        g_c = s;
    }
}

// ---------------- K1: neighbor lists (structure identical across b) ----------------
__global__ void k1_build(const int* __restrict__ ei) {
    const int v = threadIdx.x;   // 64 threads, 1 block
    int deg = 0, ecnt = 0;
    for (int e = 0; e < E_; ++e) {
        int s = ei[e];
        if (s == v) {
            int dd = ei[BE_ + e];
            int slot = -1;
            for (int k = 0; k < deg; ++k)
                if (g_ndst[v*SLOTS + k] == dd) { slot = k; break; }
            if (slot < 0 && deg < SLOTS) { slot = deg; g_ndst[v*SLOTS + deg] = dd; ++deg; }
            if (slot >= 0) g_eslot[e] = slot;
            if (ecnt < MAXE) g_vedge[v*MAXE + ecnt++] = e;
        }
    }
    g_ndeg[v] = deg;
    g_ecnt[v] = ecnt;
    for (int b = 0; b < B_; ++b)
        for (int k = 0; k < SLOTS; ++k)
            g_adjw[(b*V_ + v)*SLOTS + k] = 0.f;
}

// ---------------- K1b: accumulate adjacency weights per (b, src, slot) ----------------
__global__ void k1b_adjw(const int* __restrict__ ei, const float* __restrict__ ew) {
    const int i = blockIdx.x * blockDim.x + threadIdx.x;   // 0 .. B*E-1
    if (i >= BE_) return;
    const int e = i & (E_ - 1);
    const int b = i >> 10;
    const int v = ei[i];
    const int slot = g_eslot[e];
    atomicAdd(&g_adjw[(b*V_ + v)*SLOTS + slot], ew[i]);
}

// ---------------- K2: fused per-(b,l) attention ----------------
// smem word layout (floats):
//   sH 64*260 | sT 64*260 | sMs 32*256 | sP 64 | sR 64 | sS 64*16 | sAdj 64*16
//   | sDst 64*16 (int) | sVedge 64*32 (int) | sDeg 64 | sEcnt 64
#define SMEM_WORDS (64*260 + 64*260 + 32*256 + 64 + 64 + 64*SLOTS + 64*SLOTS + 64*SLOTS + 64*MAXE + 64 + 64)
#define SMEM_BYTES (SMEM_WORDS * 4)

__global__ void __launch_bounds__(256, 1) k2_main(
    const float* __restrict__ hs, const float* __restrict__ attn_skip,
    float* __restrict__ ew_out) {
    extern __shared__ float sm[];
    float* sH    = sm;
    float* sT    = sH + 64*260;
    float* sMs   = sT + 64*260;
    float* sP    = sMs + 32*256;
    float* sR    = sP + 64;
    float* sS    = sR + 64;
    float* sAdj  = sS + 64*SLOTS;
    int*   sDst  = (int*)(sAdj + 64*SLOTS);
    int*   sVed  = sDst + 64*SLOTS;
    int*   sDeg  = sVed + 64*MAXE;
    int*   sEcnt = sDeg + 64;

    const int tid = threadIdx.x;
    const int b = blockIdx.x >> 10;
    const int l = blockIdx.x & 1023;

    // metadata
    if (tid < 64) { sDeg[tid] = g_ndeg[tid]; sEcnt[tid] = g_ecnt[tid]; }
    for (int i = tid; i < 64*SLOTS; i += 256) { sDst[i] = g_ndst[i]; sAdj[i] = g_adjw[b*64*SLOTS + i]; }
    for (int i = tid; i < 64*MAXE; i += 256) sVed[i] = g_vedge[i];

    // load H_bl : 64 nodes x 256 dims
    for (int i = tid; i < 64*64; i += 256) {
        const int v = i >> 6, c = i & 63;
        float4 val = ((const float4*)(hs + (((size_t)(b*64 + v))*1024 + l)*256))[c];
        *(float4*)&sH[v*260 + c*4] = val;
    }
    __syncthreads();

    // p_v = H.u, r_v = H.t
    if (tid < 128) {
        const int v = tid & 63;
        const float* vec = (tid < 64) ? g_u : g_t;
        float s = 0.f;
#pragma unroll 8
        for (int c = 0; c < 64; ++c) {
            float4 h = *(const float4*)&sH[v*260 + c*4];
            float4 w = ((const float4*)vec)[c];
            s += h.x*w.x + h.y*w.y + h.z*w.z + h.w*w.w;
        }
        if (tid < 64) sP[v] = s; else sR[v] = s;
    }

    // T = H @ M.  warp w owns rows v0..v0+7, lane owns cols j0..j0+7.
    const int lane = tid & 31, warp = tid >> 5;
    const int v0 = warp * 8, j0 = lane * 8;
    unsigned long long acc[8][4];
#pragma unroll
    for (int v = 0; v < 8; ++v)
#pragma unroll
        for (int jp = 0; jp < 4; ++jp) acc[v][jp] = 0ULL;

    for (int dc = 0; dc < 8; ++dc) {
        __syncthreads();   // previous chunk fully consumed
        for (int i = tid; i < 32*64; i += 256) {
            const int r = i >> 6, c = i & 63;
            ((float4*)sMs)[r*64 + c] = ((const float4*)g_M)[(dc*32 + r)*64 + c];
        }
        __syncthreads();
#pragma unroll 2
        for (int d4 = 0; d4 < 8; ++d4) {
            float4 hreg[8];
#pragma unroll
            for (int v = 0; v < 8; ++v)
                hreg[v] = *(const float4*)&sH[(v0 + v)*260 + dc*32 + d4*4];
#pragma unroll
            for (int dd = 0; dd < 4; ++dd) {
                const int d = d4*4 + dd;
                ulonglong2 mA = *(const ulonglong2*)&sMs[d*256 + j0];
                ulonglong2 mB = *(const ulonglong2*)&sMs[d*256 + j0 + 4];
                const unsigned long long m0 = mA.x, m1 = mA.y, m2 = mB.x, m3 = mB.y;
#pragma unroll
                for (int v = 0; v < 8; ++v) {
                    const float h = (dd == 0) ? hreg[v].x : (dd == 1) ? hreg[v].y
                                   : (dd == 2) ? hreg[v].z : hreg[v].w;
                    unsigned long long hh;
                    asm("mov.b64 %0, {%1, %1};" : "=l"(hh) : "f"(h));
                    asm("fma.rn.f32x2 %0, %1, %2, %0;" : "+l"(acc[v][0]) : "l"(hh), "l"(m0));
                    asm("fma.rn.f32x2 %0, %1, %2, %0;" : "+l"(acc[v][1]) : "l"(hh), "l"(m1));
                    asm("fma.rn.f32x2 %0, %1, %2, %0;" : "+l"(acc[v][2]) : "l"(hh), "l"(m2));
                    asm("fma.rn.f32x2 %0, %1, %2, %0;" : "+l"(acc[v][3]) : "l"(hh), "l"(m3));
                }
            }
        }
    }
    // store T
#pragma unroll
    for (int v = 0; v < 8; ++v)
#pragma unroll
        for (int jp = 0; jp < 4; ++jp)
            *(unsigned long long*)&sT[(v0 + v)*260 + j0 + jp*2] = acc[v][jp];
    __syncthreads();

    // edge dots: S[v][slot] = (T_v . H_dst + p_v + r_dst + c) / 16
    {
        const int v = tid >> 2, sg = tid & 3;
        const int deg = sDeg[v];
        int dst[4];
#pragma unroll
        for (int s = 0; s < 4; ++s) {
            const int slot = sg*4 + s;
            dst[s] = (slot < deg) ? sDst[v*SLOTS + slot] : 0;
        }
        unsigned long long a0[4] = {0,0,0,0}, a1[4] = {0,0,0,0};
#pragma unroll 4
        for (int c = 0; c < 64; ++c) {
            ulonglong2 t2 = *(const ulonglong2*)&sT[v*260 + c*4];
#pragma unroll
            for (int s = 0; s < 4; ++s) {
                ulonglong2 h2 = *(const ulonglong2*)&sH[dst[s]*260 + c*4];
                asm("fma.rn.f32x2 %0, %1, %2, %0;" : "+l"(a0[s]) : "l"(t2.x), "l"(h2.x));
                asm("fma.rn.f32x2 %0, %1, %2, %0;" : "+l"(a1[s]) : "l"(t2.y), "l"(h2.y));
            }
        }
        const float cC = g_c;
#pragma unroll
        for (int s = 0; s < 4; ++s) {
            const int slot = sg*4 + s;
            if (slot < deg) {
                float2 x = u64_to_f2(a0[s]);
                float2 y = u64_to_f2(a1[s]);
                const float r = (x.x + x.y) + (y.x + y.y);
                sS[v*SLOTS + slot] = (r + sP[v] + sR[dst[s]] + cC) * 0.0625f;
            }
        }
    }
    __syncthreads();

    // softmax over slots + per-edge output
    if (tid < 64) {
        const int v = tid, deg = sDeg[v];
        float mx = -1e30f;
        for (int k = 0; k < deg; ++k) mx = fmaxf(mx, sS[v*SLOTS + k]);
        float sum = 0.f;
        for (int k = 0; k < deg; ++k) {
            const float e = __expf(sS[v*SLOTS + k] - mx);
            sS[v*SLOTS + k] = e;
            sum += e;
        }
        const float inv = 1.f / sum;
        const float ask = *attn_skip, osk = 1.f - ask;
        const int ecnt = sEcnt[v];
        for (int j = 0; j < ecnt; ++j) {
            const int e = sVed[v*MAXE + j];
            const int slot = g_eslot[e];
            const float gval = ask * sAdj[v*SLOTS + slot] + osk * (sS[v*SLOTS + slot] * inv);
            ew_out[((size_t)(b*E_ + e))*L_ + l] = gval;
        }
    }
}

// ---------------- K3: ei broadcast output ----------------
__global__ void k3_ei(const int* __restrict__ ei, float* __restrict__ out) {
    const size_t i = (size_t)blockIdx.x * blockDim.x + threadIdx.x;
    const size_t n = (size_t)2 * BE_ * L_;
    if (i < n) out[i] = (float)ei[i >> 10];
}

// ---------------- launch ----------------
extern "C" void kernel_launch(void* const* d_in, const int* in_sizes, int n_in,
                              void* d_out, int out_size) {
    const float* hs  = (const float*)d_in[0];
    const int*   ei  = (const int*)d_in[1];
    const float* ew  = (const float*)d_in[2];
    const float* Wq  = (const float*)d_in[3];
    const float* bq  = (const float*)d_in[4];
    const float* Wk  = (const float*)d_in[5];
    const float* bk  = (const float*)d_in[6];
    const float* ask = (const float*)d_in[7];

    float* out = (float*)d_out;
    const int EW_ELEMS = BE_ * L_;            // 4,194,304
    const int EI_ELEMS = 2 * BE_ * L_;        // 8,388,608
    float* ew_out = out;
    bool write_ei = false;
    if (out_size >= EI_ELEMS + EW_ELEMS) {    // concatenated (ei, ew_out)
        write_ei = true;
        ew_out = out + EI_ELEMS;
    }

    cudaFuncSetAttribute(k2_main, cudaFuncAttributeMaxDynamicSharedMemorySize, SMEM_BYTES);

    k0_prep<<<D_, D_>>>(Wq, bq, Wk, bk);
    k1_build<<<1, V_>>>(ei);
    k1b_adjw<<<(BE_ + 255)/256, 256>>>(ei, ew);
    k2_main<<<B_*L_, 256, SMEM_BYTES>>>(hs, ask, ew_out);
    if (write_ei) k3_ei<<<(EI_ELEMS + 255)/256, 256>>>(ei, out);
}

// round 4
// speedup vs baseline: 1.1763x; 1.1763x over previous
#include <cuda_runtime.h>
#include <cstdint>
#include <cstddef>

#define B_ 4
#define V_ 64
#define E_ 1024
#define L_ 1024
#define D_ 256
#define BE_ (B_*E_)
#define SLOTS 16
#define MAXE 32
#define HSTR 268          // padded row stride for sH / sT (conflict-free)

// ---------------- device scratch ----------------
__device__ __align__(16) float g_Mi[D_*D_];  // interleaved: g_Mi[(d>>1)*512 + j*2 + (d&1)]
__device__ __align__(16) float g_u[D_];      // u = Wq^T bk
__device__ __align__(16) float g_t[D_];      // t = Wk^T bq
__device__ float g_c;               // bq . bk
__device__ int   g_ndeg[V_];
__device__ int   g_ecnt[V_];
__device__ int   g_ndst[V_*SLOTS];
__device__ int   g_vedge[V_*MAXE];  // packed: e | (slot<<16)
__device__ int   g_eslot[E_];
__device__ float g_adjw[B_*V_*SLOTS];

__device__ __forceinline__ float2 u64_to_f2(unsigned long long a) {
    float2 r;
    asm("mov.b64 {%0, %1}, %2;" : "=f"(r.x), "=f"(r.y) : "l"(a));
    return r;
}
#define FMA2(acc, a, b) asm("fma.rn.f32x2 %0, %1, %2, %0;" : "+l"(acc) : "l"(a), "l"(b))

// ---------------- K0: Mi (interleaved), u, t, c ----------------
__global__ void k0_prep(const float* __restrict__ Wq, const float* __restrict__ bq,
                        const float* __restrict__ Wk, const float* __restrict__ bk) {
    __shared__ float swk[D_];
    const int j = blockIdx.x, d = threadIdx.x;
    swk[d] = Wk[d*D_ + j];
    __syncthreads();
    float acc = 0.f;
#pragma unroll 8
    for (int k = 0; k < D_; ++k) acc += Wq[k*D_ + d] * swk[k];
    g_Mi[(d>>1)*512 + j*2 + (d&1)] = acc;
    if (d == 0) {
        float s = 0.f;
        for (int k = 0; k < D_; ++k) s += bq[k] * swk[k];
        g_t[j] = s;
    }
    if (j == 0) {
        float s = 0.f;
        for (int k = 0; k < D_; ++k) s += Wq[k*D_ + d] * bk[k];
        g_u[d] = s;
    }
    if (j == 0 && d == 0) {
        float s = 0.f;
        for (int k = 0; k < D_; ++k) s += bq[k] * bk[k];
        g_c = s;
    }
}

// ---------------- K1: neighbor lists (structure identical across b) ----------------
__global__ void k1_build(const int* __restrict__ ei) {
    const int v = threadIdx.x;   // 64 threads, 1 block
    int deg = 0, ecnt = 0;
    for (int e = 0; e < E_; ++e) {
        int s = ei[e];
        if (s == v) {
            int dd = ei[BE_ + e];
            int slot = -1;
            for (int k = 0; k < deg; ++k)
                if (g_ndst[v*SLOTS + k] == dd) { slot = k; break; }
            if (slot < 0 && deg < SLOTS) { slot = deg; g_ndst[v*SLOTS + deg] = dd; ++deg; }
            if (slot >= 0) {
                g_eslot[e] = slot;
                if (ecnt < MAXE) g_vedge[v*MAXE + ecnt++] = e | (slot << 16);
            }
        }
    }
    g_ndeg[v] = deg;
    g_ecnt[v] = ecnt;
    for (int b = 0; b < B_; ++b)
        for (int k = 0; k < SLOTS; ++k)
            g_adjw[(b*V_ + v)*SLOTS + k] = 0.f;
}

// ---------------- K1b: adjacency weight sums ----------------
__global__ void k1b_adjw(const int* __restrict__ ei, const float* __restrict__ ew) {
    const int i = blockIdx.x * blockDim.x + threadIdx.x;
    if (i >= BE_) return;
    const int e = i & (E_ - 1);
    const int b = i >> 10;
    const int v = ei[i];
    const int slot = g_eslot[e];
    atomicAdd(&g_adjw[(b*V_ + v)*SLOTS + slot], ew[i]);
}

// ---------------- K2: fused per-(b,l) attention ----------------
// floats: sH 64*268 | sU 64*268 (M dbl-buf then T) | sP 64 | sR 64 | sS 1024
//         | sAdj 1024 | sDst 1024 | sVed 2048 | sDeg 64 | sEcnt 64
#define SMEM_WORDS (64*HSTR + 64*HSTR + 64 + 64 + 1024 + 1024 + 1024 + 2048 + 64 + 64)
#define SMEM_BYTES (SMEM_WORDS * 4)

__global__ void __launch_bounds__(512, 1) k2_main(
    const float* __restrict__ hs, const float* __restrict__ attn_skip,
    float* __restrict__ ew_out) {
    extern __shared__ float sm[];
    float* sH    = sm;
    float* sU    = sH + 64*HSTR;      // M chunk buf0 [0..8191], buf1 [8192..16383]; later T (stride HSTR)
    float* sP    = sU + 64*HSTR;
    float* sR    = sP + 64;
    float* sS    = sR + 64;
    float* sAdj  = sS + 64*SLOTS;
    int*   sDst  = (int*)(sAdj + 64*SLOTS);
    int*   sVed  = sDst + 64*SLOTS;
    int*   sDeg  = sVed + 64*MAXE;
    int*   sEcnt = sDeg + 64;

    const int tid = threadIdx.x;
    const int b = blockIdx.x >> 10;
    const int l = blockIdx.x & 1023;

    // metadata (full coverage!)
    if (tid < 64) { sDeg[tid] = g_ndeg[tid]; sEcnt[tid] = g_ecnt[tid]; }
    for (int i = tid; i < 64*SLOTS; i += 512) {
        sDst[i] = g_ndst[i];
        sAdj[i] = g_adjw[b*64*SLOTS + i];
    }
    for (int i = tid; i < 64*MAXE; i += 512) sVed[i] = g_vedge[i];

    // load H_bl : 64 nodes x 256 dims
#pragma unroll
    for (int it = 0; it < 8; ++it) {
        const int i = tid + it*512;
        const int v = i >> 6, c = i & 63;
        float4 val = ((const float4*)(hs + (((size_t)(b*64 + v))*1024 + l)*256))[c];
        *(float4*)&sH[v*HSTR + c*4] = val;
    }

    // prefetch M chunk 0
    const float4* gMi4 = (const float4*)g_Mi;   // chunk c = float4 [c*2048, +2048)
    float4 stage[4];
#pragma unroll
    for (int s = 0; s < 4; ++s) stage[s] = gMi4[tid + s*512];

    __syncthreads();   // sH ready

    // store chunk 0 into buf0
#pragma unroll
    for (int s = 0; s < 4; ++s) ((float4*)sU)[tid + s*512] = stage[s];

    // p_v = H.u, r_v = H.t
    if (tid < 128) {
        const int v = tid & 63;
        const float* vec = (tid < 64) ? g_u : g_t;
        float s = 0.f;
#pragma unroll 8
        for (int c = 0; c < 64; ++c) {
            float4 h = *(const float4*)&sH[v*HSTR + c*4];
            float4 w = ((const float4*)vec)[c];
            s += h.x*w.x + h.y*w.y + h.z*w.z + h.w*w.w;
        }
        if (tid < 64) sP[v] = s; else sR[v] = s;
    }

    // ---- T = H @ M ----
    // warp tile 32v x 32j; lane tile 4v x 8j (j = jb + p*8 + {0,1})
    const int lane = tid & 31, warp = tid >> 5;
    const int warpV = warp >> 3, warpJ = warp & 7;
    const int laneV = lane >> 2, laneJ = lane & 3;
    const int v0 = warpV*32 + laneV*4;
    const int jb = warpJ*32 + laneJ*2;

    unsigned long long acc[4][8];
#pragma unroll
    for (int v = 0; v < 4; ++v)
#pragma unroll
        for (int j = 0; j < 8; ++j) acc[v][j] = 0ULL;

    for (int c = 0; c < 8; ++c) {
        if (c + 1 < 8) {
#pragma unroll
            for (int s = 0; s < 4; ++s) stage[s] = gMi4[(c+1)*2048 + tid + s*512];
        }
        __syncthreads();   // buf[c&1] filled; prior compute done

        const unsigned long long* Mb = (const unsigned long long*)(sU + (c & 1)*8192);
        const int cbase = c*32;
#pragma unroll
        for (int ss = 0; ss < 8; ++ss) {
            ulonglong2 hv[4];
#pragma unroll
            for (int v = 0; v < 4; ++v)
                hv[v] = *(const ulonglong2*)&sH[(v0 + v)*HSTR + cbase + ss*4];
            const unsigned long long* ra = Mb + (ss*2    )*256 + jb;
            const unsigned long long* rb = Mb + (ss*2 + 1)*256 + jb;
#pragma unroll
            for (int p = 0; p < 4; ++p) {
                ulonglong2 ma = *(const ulonglong2*)(ra + p*8);
                ulonglong2 mb = *(const ulonglong2*)(rb + p*8);
#pragma unroll
                for (int v = 0; v < 4; ++v) {
                    FMA2(acc[v][2*p  ], hv[v].x, ma.x);
                    FMA2(acc[v][2*p+1], hv[v].x, ma.y);
                    FMA2(acc[v][2*p  ], hv[v].y, mb.x);
                    FMA2(acc[v][2*p+1], hv[v].y, mb.y);
                }
            }
        }
        if (c + 1 < 8) {
            float4* dst = (float4*)(sU + ((c+1) & 1)*8192);
#pragma unroll
            for (int s = 0; s < 4; ++s) dst[tid + s*512] = stage[s];
        }
    }
    __syncthreads();   // all GEMM reads of sU done before T overwrites it

    // store T (combine even/odd-d partial sums)
    float* sT = sU;
#pragma unroll
    for (int v = 0; v < 4; ++v) {
#pragma unroll
        for (int p = 0; p < 4; ++p) {
            float2 a = u64_to_f2(acc[v][2*p]);
            float2 bb = u64_to_f2(acc[v][2*p+1]);
            float2 st = make_float2(a.x + a.y, bb.x + bb.y);
            *(float2*)&sT[(v0 + v)*HSTR + jb + p*8] = st;
        }
    }
    __syncthreads();

    // ---- edge dots: S[v][slot] = (T_v . H_dst + p_v + r_dst + c) / 16 ----
    {
        const int v = tid >> 3, sub = tid & 7;
        const int deg = sDeg[v];
        const int s0 = sub*2, s1 = sub*2 + 1;
        const int d0 = (s0 < deg) ? sDst[v*SLOTS + s0] : 0;
        const int d1 = (s1 < deg) ? sDst[v*SLOTS + s1] : 0;
        unsigned long long a00 = 0, a01 = 0, a10 = 0, a11 = 0;
#pragma unroll 4
        for (int c = 0; c < 64; ++c) {
            ulonglong2 t2 = *(const ulonglong2*)&sT[v*HSTR + c*4];
            ulonglong2 h0 = *(const ulonglong2*)&sH[d0*HSTR + c*4];
            ulonglong2 h1 = *(const ulonglong2*)&sH[d1*HSTR + c*4];
            FMA2(a00, t2.x, h0.x); FMA2(a01, t2.y, h0.y);
            FMA2(a10, t2.x, h1.x); FMA2(a11, t2.y, h1.y);
        }
        const float cC = g_c;
        if (s0 < deg) {
            float2 x = u64_to_f2(a00), y = u64_to_f2(a01);
            sS[v*SLOTS + s0] = ((x.x + x.y) + (y.x + y.y) + sP[v] + sR[d0] + cC) * 0.0625f;
        }
        if (s1 < deg) {
            float2 x = u64_to_f2(a10), y = u64_to_f2(a11);
            sS[v*SLOTS + s1] = ((x.x + x.y) + (y.x + y.y) + sP[v] + sR[d1] + cC) * 0.0625f;
        }
    }
    __syncthreads();

    // ---- softmax + per-edge output ----
    if (tid < 64) {
        const int v = tid, deg = sDeg[v];
        float mx = -1e30f;
        for (int k = 0; k < deg; ++k) mx = fmaxf(mx, sS[v*SLOTS + k]);
        float sum = 0.f;
        for (int k = 0; k < deg; ++k) {
            const float e = __expf(sS[v*SLOTS + k] - mx);
            sS[v*SLOTS + k] = e;
            sum += e;
        }
        const float inv = 1.f / sum;
        const float ask = *attn_skip, osk = 1.f - ask;
        const int ecnt = sEcnt[v];
        for (int j = 0; j < ecnt; ++j) {
            const int w = sVed[v*MAXE + j];
            const int e = w & 0xFFFF, slot = w >> 16;
            const float gval = ask * sAdj[v*SLOTS + slot] + osk * (sS[v*SLOTS + slot] * inv);
            ew_out[((size_t)(b*E_ + e))*L_ + l] = gval;
        }
    }
}

// ---------------- K3: ei broadcast output ----------------
__global__ void k3_ei(const int* __restrict__ ei, float* __restrict__ out) {
    const size_t i = (size_t)blockIdx.x * blockDim.x + threadIdx.x;
    const size_t n = (size_t)2 * BE_ * L_;
    if (i < n) out[i] = (float)ei[i >> 10];
}

// ---------------- launch ----------------
extern "C" void kernel_launch(void* const* d_in, const int* in_sizes, int n_in,
                              void* d_out, int out_size) {
    const float* hs  = (const float*)d_in[0];
    const int*   ei  = (const int*)d_in[1];
    const float* ew  = (const float*)d_in[2];
    const float* Wq  = (const float*)d_in[3];
    const float* bq  = (const float*)d_in[4];
    const float* Wk  = (const float*)d_in[5];
    const float* bk  = (const float*)d_in[6];
    const float* ask = (const float*)d_in[7];

    float* out = (float*)d_out;
    const int EW_ELEMS = BE_ * L_;
    const int EI_ELEMS = 2 * BE_ * L_;
    float* ew_out = out;
    bool write_ei = false;
    if (out_size >= EI_ELEMS + EW_ELEMS) {
        write_ei = true;
        ew_out = out + EI_ELEMS;
    }

    cudaFuncSetAttribute(k2_main, cudaFuncAttributeMaxDynamicSharedMemorySize, SMEM_BYTES);

    k0_prep<<<D_, D_>>>(Wq, bq, Wk, bk);
    k1_build<<<1, V_>>>(ei);
    k1b_adjw<<<(BE_ + 255)/256, 256>>>(ei, ew);
    k2_main<<<B_*L_, 512, SMEM_BYTES>>>(hs, ask, ew_out);
    if (write_ei) k3_ei<<<(EI_ELEMS + 255)/256, 256>>>(ei, out);
}